// round 16
// baseline (speedup 1.0000x reference)
#include <cuda_runtime.h>
#include <cuda_fp16.h>
#include <cstdint>
#include <math.h>

// ============================================================================
// ScaledDotAttention via mma.sync (HMMA fp16), sm_103-compatible PTX only.
//   out = softmax((Q.Mem^T/sqrt(D)) * W) . Mem     Q=4096, M=8192, D=128 fp32
//
// Round 16 vs R15 (90.6 us; measured tile time ~= SUM of crossbar+tensor
// floors -> phases serialize inside each warp):
//  - CROSS-TILE SOFTWARE PIPELINE: fused 8-step inner loop executes
//    S(tile t) and PV(tile t-1) interleaved (step = S k-step + PV nf-group,
//    independent streams) so ldsm stalls of one stream are covered by mma
//    of the other. PV consumes aPrev (P fragments of t-1, registers).
//  - stage ring 2 -> 3 (live tiles: t-1 PV, t S, t+1 inflight); smem 104KB.
//  - math/order per accumulator unchanged -> bitwise-identical output.
// ============================================================================

namespace {
constexpr int QT = 4096, MT = 8192, DD = 128;
constexpr int BQ = 32, BM = 128;
constexpr int THREADS = 256;
constexpr int NCTA = 147, UPC = 7, NUNITS = 1024;   // unit=(qt,jc): 128x8
constexpr float SCALE = 0.088388347648318440550f;   // 1/sqrt(128)

// smem layout (bytes)
constexpr int S_QH = 0;           // Q hi [2 d-halves][32 rows][128B] = 8KB
constexpr int S_M  = 8192;        // 4 pairs x 3 stages x 8KB = 96KB
constexpr int STG  = 8192;        // one stage = 32 rows x 256B
constexpr int PSTRIDE = 3 * STG;  // per-pair
constexpr int S_LSUM = S_M + 4 * PSTRIDE;   // 106496
constexpr int SMEM_TOTAL = S_LSUM + 256;
// epilogue sO ([32][128] fp32 = 16KB) reuses the S_M region
}

// preprocessed operands + partial-result slabs
__device__ __align__(16) __half g_q_h[QT * DD];
__device__ __align__(16) __half g_m_h[MT * DD];
__device__ __align__(16) float g_out_part[2][(size_t)QT * DD];
__device__ float g_lsum_part[2][QT];

// ---------------- helpers ----------------
__device__ __forceinline__ uint32_t smem_to_u32(const void* p) {
    uint32_t a;
    asm("{ .reg .u64 t; cvta.to.shared.u64 t, %1; cvt.u32.u64 %0, t; }" : "=r"(a) : "l"(p));
    return a;
}
__device__ __forceinline__ uint32_t sw128(uint32_t o) { return o ^ ((o >> 3) & 0x70); }

__device__ __forceinline__ void ldsm_x4(uint32_t* r, uint32_t a) {
    asm volatile("ldmatrix.sync.aligned.m8n8.x4.shared.b16 {%0,%1,%2,%3}, [%4];"
                 : "=r"(r[0]), "=r"(r[1]), "=r"(r[2]), "=r"(r[3]) : "r"(a));
}
__device__ __forceinline__ void ldsm_x4t(uint32_t* r, uint32_t a) {
    asm volatile("ldmatrix.sync.aligned.m8n8.x4.trans.shared.b16 {%0,%1,%2,%3}, [%4];"
                 : "=r"(r[0]), "=r"(r[1]), "=r"(r[2]), "=r"(r[3]) : "r"(a));
}
__device__ __forceinline__ void mma_f16(float* c, const uint32_t* a, const uint32_t* b) {
    asm volatile("mma.sync.aligned.m16n8k16.row.col.f32.f16.f16.f32 "
                 "{%0,%1,%2,%3}, {%4,%5,%6,%7}, {%8,%9}, {%0,%1,%2,%3};"
                 : "+f"(c[0]), "+f"(c[1]), "+f"(c[2]), "+f"(c[3])
                 : "r"(a[0]), "r"(a[1]), "r"(a[2]), "r"(a[3]), "r"(b[0]), "r"(b[1]));
}
__device__ __forceinline__ uint32_t pack_h2(float a, float b) {
    __half2 v = __floats2half2_rn(a, b);   // .x = a
    return *reinterpret_cast<uint32_t*>(&v);
}
#define CP_ASYNC16(dst, src) \
    asm volatile("cp.async.cg.shared.global [%0], [%1], 16;" :: "r"(dst), "l"(src))
#define CP_COMMIT() asm volatile("cp.async.commit_group;" ::: "memory")
#define CP_WAIT0()  asm volatile("cp.async.wait_group 0;" ::: "memory")
#define BAR_PAIR(id) asm volatile("bar.sync %0, 64;" :: "r"(id) : "memory")

// ---------------- prep: fp32 -> fp16, float4 vectorized ----------------
__global__ void prep_kernel(const float* __restrict__ q, const float* __restrict__ m) {
    int i4 = (blockIdx.x * blockDim.x + threadIdx.x) * 4;
    if (i4 < QT * DD) {
        float4 v = *(const float4*)(q + i4);
        *(__half2*)(g_q_h + i4)     = __floats2half2_rn(v.x, v.y);
        *(__half2*)(g_q_h + i4 + 2) = __floats2half2_rn(v.z, v.w);
    } else {
        int mi = i4 - QT * DD;
        if (mi < MT * DD) {
            float4 v = *(const float4*)(m + mi);
            *(__half2*)(g_m_h + mi)     = __floats2half2_rn(v.x, v.y);
            *(__half2*)(g_m_h + mi + 2) = __floats2half2_rn(v.z, v.w);
        }
    }
}

// ---------------- main persistent kernel ----------------
__global__ __launch_bounds__(THREADS, 1)
void attn_mma_kernel(const float* __restrict__ weights)
{
    extern __shared__ char smem[];
    const uint32_t sb = smem_to_u32(smem);
    const int tid  = threadIdx.x;
    const int wid  = tid >> 5;
    const int lane = tid & 31;
    const int mw   = wid & 1;         // q-row group inside pair
    const int pw   = wid >> 1;        // pair id == j-quarter id (0..3)
    const int gid  = lane >> 2;
    const int tig  = lane & 3;
    const int qrow0 = mw * 16;
    const int j0w   = pw * 32;
    const int barid = 1 + pw;
    const int c = blockIdx.x;

    const int u0 = c * UPC;
    const int u1 = min(u0 + UPC, NUNITS);
    if (u0 >= NUNITS) return;
    const int qt_a = u0 >> 3, qt_b = (u1 - 1) >> 3;

    float* lsum = (float*)(smem + S_LSUM);

    // per-lane addressing (R6 geometry)
    const int rowA   = qrow0 + (lane & 15);
    const int selA   = lane >> 4;
    const int sb_row = ((lane >> 4) & 1) * 8 + (lane & 7);
    const int sb_sel = (lane >> 3) & 1;
    const int pv_row = lane & 15;
    const int pv_sel = lane >> 4;

    const uint32_t pair_base = sb + S_M + pw * PSTRIDE;

    for (int qt = qt_a; qt <= qt_b; ++qt) {
        const int s0 = max(u0, qt * 8) - qt * 8;
        const int s1 = min(u1, qt * 8 + 8) - qt * 8;
        const int t_beg = s0 * 8, t_end = s1 * 8;
        const int q0 = qt * BQ;
        const int slot = c - (8 * qt) / 7;           // 0 or 1, deterministic

        if (tid < 32) lsum[tid] = 0.f;

        // ---- load Q tile to smem, hoist A-fragments to registers ----
        for (int it = tid; it < 32 * 16; it += THREADS) {
            int row = it >> 4, ch = it & 15;
            uint32_t o = sw128((uint32_t)((ch >> 3) * 4096 + row * 128 + (ch & 7) * 16));
            *(uint4*)(smem + S_QH + o) = *(const uint4*)(g_q_h + (size_t)(q0 + row) * DD + ch * 8);
        }
        __syncthreads();

        uint32_t Aq[8][4];
        #pragma unroll
        for (int k = 0; k < 8; ++k) {
            const int half = k >> 2;
            const int cb   = (k & 3) * 2;
            uint32_t ao = sw128((uint32_t)(half * 4096 + rowA * 128 + (cb + selA) * 16));
            ldsm_x4(Aq[k], sb + S_QH + ao);
        }

        float o_acc[16][4];
        #pragma unroll
        for (int nf = 0; nf < 16; ++nf)
            #pragma unroll
            for (int e = 0; e < 4; ++e) o_acc[nf][e] = 0.f;
        float rs0 = 0.f, rs1 = 0.f;

        const float* wbase = weights + (size_t)(q0 + qrow0 + gid) * MT + j0w + tig * 2;

        auto load_quarter = [&](int t, int buf) {
            const int m0 = t * BM + j0w;
            const uint32_t qb = pair_base + buf * STG;
            int it = tid & 63;
            #pragma unroll
            for (int rep = 0; rep < 8; ++rep, it += 64) {   // 512 items / 64 thr
                int row = it >> 4, ch = it & 15;
                uint32_t o = sw128((uint32_t)((ch >> 3) * 4096 + row * 128 + (ch & 7) * 16));
                CP_ASYNC16(qb + o, (const void*)(g_m_h + (size_t)(m0 + row) * DD + ch * 8));
            }
        };

        auto load_wreg = [&](int t, float (&wreg)[4][4]) {
            const float* wp = wbase + (size_t)t * BM;
            #pragma unroll
            for (int nf = 0; nf < 4; ++nf) {
                float2 w0 = *(const float2*)(wp + nf * 8);
                float2 w1 = *(const float2*)(wp + nf * 8 + (size_t)8 * MT);
                wreg[nf][0] = w0.x * SCALE; wreg[nf][1] = w0.y * SCALE;
                wreg[nf][2] = w1.x * SCALE; wreg[nf][3] = w1.y * SCALE;
            }
        };

        // exp + pack P fragments (tile t) into aP
        auto softmax_pack = [&](const float (&sf)[4][4], const float (&wreg)[4][4],
                                uint32_t (&aP)[2][4]) {
            #pragma unroll
            for (int nf = 0; nf < 4; ++nf) {
                float p[4];
                #pragma unroll
                for (int e = 0; e < 4; ++e) p[e] = __expf(sf[nf][e] * wreg[nf][e]);
                rs0 += p[0] + p[1];
                rs1 += p[2] + p[3];
                const int kf = nf >> 1;
                const int hi = (nf & 1) * 2;
                aP[kf][hi]     = pack_h2(p[0], p[1]);
                aP[kf][hi + 1] = pack_h2(p[2], p[3]);
            }
        };

        uint32_t aPrev[2][4];

        load_quarter(t_beg, t_beg % 3);
        CP_COMMIT();

        // ---- peeled first tile: S only ----
        {
            const int t = t_beg;
            CP_WAIT0();
            BAR_PAIR(barid);
            if (t + 1 < t_end) load_quarter(t + 1, (t + 1) % 3);
            CP_COMMIT();
            const uint32_t mh = pair_base + (t % 3) * STG;

            float wreg[4][4];
            load_wreg(t, wreg);

            float sf[4][4];
            #pragma unroll
            for (int nf = 0; nf < 4; ++nf)
                #pragma unroll
                for (int e = 0; e < 4; ++e) sf[nf][e] = 0.f;

            #pragma unroll
            for (int st = 0; st < 8; ++st) {
                const int half = st >> 2, cb = (st & 3) * 2;
                uint32_t Bh[8];
                #pragma unroll
                for (int nfb = 0; nfb < 4; nfb += 2) {
                    uint32_t bo = sw128((uint32_t)(half * 4096 + (nfb * 8 + sb_row) * 128
                                        + (cb + sb_sel) * 16));
                    ldsm_x4(Bh + nfb * 2, mh + bo);
                }
                #pragma unroll
                for (int nf = 0; nf < 4; ++nf) mma_f16(sf[nf], Aq[st], Bh + nf * 2);
            }
            softmax_pack(sf, wreg, aPrev);
        }

        // ---- steady state: S(t) fused with PV(t-1) ----
        for (int t = t_beg + 1; t < t_end; ++t) {
            CP_WAIT0();
            BAR_PAIR(barid);
            if (t + 1 < t_end) load_quarter(t + 1, (t + 1) % 3);
            CP_COMMIT();

            const uint32_t mh  = pair_base + (t % 3) * STG;          // tile t
            const uint32_t mhp = pair_base + ((t + 2) % 3) * STG;    // tile t-1

            float wreg[4][4];
            load_wreg(t, wreg);

            float sf[4][4];
            #pragma unroll
            for (int nf = 0; nf < 4; ++nf)
                #pragma unroll
                for (int e = 0; e < 4; ++e) sf[nf][e] = 0.f;

            #pragma unroll
            for (int st = 0; st < 8; ++st) {
                // --- S stream: k-step st on tile t ---
                const int half = st >> 2, cb = (st & 3) * 2;
                uint32_t Bh[8];
                #pragma unroll
                for (int nfb = 0; nfb < 4; nfb += 2) {
                    uint32_t bo = sw128((uint32_t)(half * 4096 + (nfb * 8 + sb_row) * 128
                                        + (cb + sb_sel) * 16));
                    ldsm_x4(Bh + nfb * 2, mh + bo);
                }
                // --- PV stream: group st on tile t-1 ---
                const int kf = st >> 2, nfg = (st & 3) * 4;
                const int jb = (kf * 16 + pv_row) * 128;
                uint32_t Ph[8];
                #pragma unroll
                for (int nfb = 0; nfb < 4; nfb += 2) {
                    const int nf = nfg + nfb;
                    uint32_t bo = sw128((uint32_t)((nf >> 3) * 4096 + jb
                                        + ((nf & 7) + pv_sel) * 16));
                    ldsm_x4t(Ph + nfb * 2, mhp + bo);
                }
                #pragma unroll
                for (int nf = 0; nf < 4; ++nf) mma_f16(sf[nf], Aq[st], Bh + nf * 2);
                #pragma unroll
                for (int nfb = 0; nfb < 4; ++nfb)
                    mma_f16(o_acc[nfg + nfb], aPrev[kf], Ph + nfb * 2);
            }
            softmax_pack(sf, wreg, aPrev);   // after PV consumed old aPrev
        }

        // ---- drain: PV of last tile ----
        {
            const uint32_t mhp = pair_base + ((t_end - 1) % 3) * STG;
            #pragma unroll
            for (int st = 0; st < 8; ++st) {
                const int kf = st >> 2, nfg = (st & 3) * 4;
                const int jb = (kf * 16 + pv_row) * 128;
                uint32_t Ph[8];
                #pragma unroll
                for (int nfb = 0; nfb < 4; nfb += 2) {
                    const int nf = nfg + nfb;
                    uint32_t bo = sw128((uint32_t)((nf >> 3) * 4096 + jb
                                        + ((nf & 7) + pv_sel) * 16));
                    ldsm_x4t(Ph + nfb * 2, mhp + bo);
                }
                #pragma unroll
                for (int nfb = 0; nfb < 4; ++nfb)
                    mma_f16(o_acc[nfg + nfb], aPrev[kf], Ph + nfb * 2);
            }
        }

        // ---- segment epilogue: reduce + write partial slabs ----
        rs0 += __shfl_xor_sync(0xffffffffu, rs0, 1);
        rs0 += __shfl_xor_sync(0xffffffffu, rs0, 2);
        rs1 += __shfl_xor_sync(0xffffffffu, rs1, 1);
        rs1 += __shfl_xor_sync(0xffffffffu, rs1, 2);
        if (tig == 0) {
            atomicAdd(&lsum[qrow0 + gid], rs0);
            atomicAdd(&lsum[qrow0 + gid + 8], rs1);
        }
        __syncthreads();

        float* sO = (float*)(smem + S_M);   // reuse Mem region: [32][128] fp32
        for (int i = tid; i < 32 * 128; i += THREADS) sO[i] = 0.f;
        __syncthreads();
        #pragma unroll
        for (int nf = 0; nf < 16; ++nf) {
            const int cbase = nf * 8 + tig * 2;
            const int r0 = qrow0 + gid;
            atomicAdd(&sO[r0 * 128 + cbase],           o_acc[nf][0]);
            atomicAdd(&sO[r0 * 128 + cbase + 1],       o_acc[nf][1]);
            atomicAdd(&sO[(r0 + 8) * 128 + cbase],     o_acc[nf][2]);
            atomicAdd(&sO[(r0 + 8) * 128 + cbase + 1], o_acc[nf][3]);
        }
        __syncthreads();

        for (int i = tid; i < 32 * 32; i += THREADS) {
            int r  = i >> 5;
            int c4 = (i & 31) * 4;
            float4 v = *(float4*)(&sO[r * 128 + c4]);
            *(float4*)(&g_out_part[slot][(size_t)(q0 + r) * DD + c4]) = v;
        }
        if (tid < 32) g_lsum_part[slot][q0 + tid] = lsum[tid];
        __syncthreads();   // done with sO/lsum before next segment
    }
}

// ---------------- combine: out = (p0+p1)/(l0+l1) ----------------
__global__ void combine_kernel(float* __restrict__ out) {
    int idx = blockIdx.x * blockDim.x + threadIdx.x;
    if (idx >= QT * (DD / 4)) return;
    int r  = idx >> 5;
    int c4 = (idx & 31) * 4;
    float inv = 1.0f / (g_lsum_part[0][r] + g_lsum_part[1][r]);
    float4 a = *(float4*)(&g_out_part[0][(size_t)r * DD + c4]);
    float4 b = *(float4*)(&g_out_part[1][(size_t)r * DD + c4]);
    float4 v;
    v.x = (a.x + b.x) * inv; v.y = (a.y + b.y) * inv;
    v.z = (a.z + b.z) * inv; v.w = (a.w + b.w) * inv;
    *(float4*)(&out[(size_t)r * DD + c4]) = v;
}

// ---------------- launch ----------------
extern "C" void kernel_launch(void* const* d_in, const int* in_sizes, int n_in,
                              void* d_out, int out_size)
{
    const float* query   = (const float*)d_in[0];
    const float* memory  = (const float*)d_in[1];
    const float* weights = (const float*)d_in[2];
    float* out = (float*)d_out;

    cudaFuncSetAttribute(attn_mma_kernel,
                         cudaFuncAttributeMaxDynamicSharedMemorySize, SMEM_TOTAL);

    prep_kernel<<<((QT + MT) * DD / 4 + 255) / 256, 256>>>(query, memory);
    attn_mma_kernel<<<NCTA, THREADS, SMEM_TOTAL>>>(weights);
    combine_kernel<<<(QT * (DD / 4) + 255) / 256, 256>>>(out);
}

// round 17
// speedup vs baseline: 1.1818x; 1.1818x over previous
#include <cuda_runtime.h>
#include <cuda_fp16.h>
#include <cstdint>
#include <math.h>

// ============================================================================
// ScaledDotAttention via mma.sync (HMMA fp16), sm_103-compatible PTX only.
//   out = softmax((Q.Mem^T/sqrt(D)) * W) . Mem     Q=4096, M=8192, D=128 fp32
//
// Round 17 (vs R15=90.6us best; R16 fused-pipeline regressed to 109 via
// register pressure -> reverted):
//  - R15 main-loop structure restored (register-resident Q, 1 bar/tile,
//    2-stage per-pair ring, single-pass fp16 GEMMs)
//  - combine kernel FOLDED into the persistent kernel: last-finisher per
//    q-tile (atomic counter zeroed by prep) normalizes and writes out.
//    -> one less launch; ncu -s 5 now lands on the main kernel.
//  - light intra-phase pipelining: 2-deep B-fragment double buffer in S and
//    PV phases (+8 regs, phases disjoint) for explicit ldsm/mma overlap.
// ============================================================================

namespace {
constexpr int QT = 4096, MT = 8192, DD = 128;
constexpr int BQ = 32, BM = 128;
constexpr int THREADS = 256;
constexpr int NCTA = 147, UPC = 7, NUNITS = 1024;   // unit=(qt,jc): 128x8
constexpr int NQT = 128;
constexpr float SCALE = 0.088388347648318440550f;   // 1/sqrt(128)

// smem layout (bytes)
constexpr int S_QH = 0;           // Q hi [2 d-halves][32 rows][128B] = 8KB
constexpr int S_M  = 8192;        // 4 pairs x 2 stages x 8KB (Mh) = 64KB
constexpr int PSTRIDE = 16384;    // per-pair (2 stages)
constexpr int STG = 8192;         // one stage = 32 rows x 256B
constexpr int S_LSUM = S_M + 65536;   // 73728
constexpr int SMEM_TOTAL = S_LSUM + 256;
// epilogue sO ([32][128] fp32 = 16KB) reuses the S_M region
}

// preprocessed operands + partial-result slabs + completion counters
__device__ __align__(16) __half g_q_h[QT * DD];
__device__ __align__(16) __half g_m_h[MT * DD];
__device__ __align__(16) float g_out_part[2][(size_t)QT * DD];
__device__ float g_lsum_part[2][QT];
__device__ int g_done[NQT];

// ---------------- helpers ----------------
__device__ __forceinline__ uint32_t smem_to_u32(const void* p) {
    uint32_t a;
    asm("{ .reg .u64 t; cvta.to.shared.u64 t, %1; cvt.u32.u64 %0, t; }" : "=r"(a) : "l"(p));
    return a;
}
__device__ __forceinline__ uint32_t sw128(uint32_t o) { return o ^ ((o >> 3) & 0x70); }

__device__ __forceinline__ void ldsm_x4(uint32_t* r, uint32_t a) {
    asm volatile("ldmatrix.sync.aligned.m8n8.x4.shared.b16 {%0,%1,%2,%3}, [%4];"
                 : "=r"(r[0]), "=r"(r[1]), "=r"(r[2]), "=r"(r[3]) : "r"(a));
}
__device__ __forceinline__ void ldsm_x4t(uint32_t* r, uint32_t a) {
    asm volatile("ldmatrix.sync.aligned.m8n8.x4.trans.shared.b16 {%0,%1,%2,%3}, [%4];"
                 : "=r"(r[0]), "=r"(r[1]), "=r"(r[2]), "=r"(r[3]) : "r"(a));
}
__device__ __forceinline__ void mma_f16(float* c, const uint32_t* a, const uint32_t* b) {
    asm volatile("mma.sync.aligned.m16n8k16.row.col.f32.f16.f16.f32 "
                 "{%0,%1,%2,%3}, {%4,%5,%6,%7}, {%8,%9}, {%0,%1,%2,%3};"
                 : "+f"(c[0]), "+f"(c[1]), "+f"(c[2]), "+f"(c[3])
                 : "r"(a[0]), "r"(a[1]), "r"(a[2]), "r"(a[3]), "r"(b[0]), "r"(b[1]));
}
__device__ __forceinline__ uint32_t pack_h2(float a, float b) {
    __half2 v = __floats2half2_rn(a, b);   // .x = a
    return *reinterpret_cast<uint32_t*>(&v);
}
#define CP_ASYNC16(dst, src) \
    asm volatile("cp.async.cg.shared.global [%0], [%1], 16;" :: "r"(dst), "l"(src))
#define CP_COMMIT() asm volatile("cp.async.commit_group;" ::: "memory")
#define CP_WAIT0()  asm volatile("cp.async.wait_group 0;" ::: "memory")
#define BAR_PAIR(id) asm volatile("bar.sync %0, 64;" :: "r"(id) : "memory")

// ---------------- prep: fp32 -> fp16 + zero completion counters ----------------
__global__ void prep_kernel(const float* __restrict__ q, const float* __restrict__ m) {
    int gidx = blockIdx.x * blockDim.x + threadIdx.x;
    if (gidx < NQT) g_done[gidx] = 0;
    int i4 = gidx * 4;
    if (i4 < QT * DD) {
        float4 v = *(const float4*)(q + i4);
        *(__half2*)(g_q_h + i4)     = __floats2half2_rn(v.x, v.y);
        *(__half2*)(g_q_h + i4 + 2) = __floats2half2_rn(v.z, v.w);
    } else {
        int mi = i4 - QT * DD;
        if (mi < MT * DD) {
            float4 v = *(const float4*)(m + mi);
            *(__half2*)(g_m_h + mi)     = __floats2half2_rn(v.x, v.y);
            *(__half2*)(g_m_h + mi + 2) = __floats2half2_rn(v.z, v.w);
        }
    }
}

// ---------------- main persistent kernel ----------------
__global__ __launch_bounds__(THREADS, 1)
void attn_mma_kernel(const float* __restrict__ weights, float* __restrict__ out)
{
    extern __shared__ char smem[];
    const uint32_t sb = smem_to_u32(smem);
    const int tid  = threadIdx.x;
    const int wid  = tid >> 5;
    const int lane = tid & 31;
    const int mw   = wid & 1;         // q-row group inside pair
    const int pw   = wid >> 1;        // pair id == j-quarter id (0..3)
    const int gid  = lane >> 2;
    const int tig  = lane & 3;
    const int qrow0 = mw * 16;
    const int j0w   = pw * 32;
    const int barid = 1 + pw;
    const int c = blockIdx.x;

    const int u0 = c * UPC;
    const int u1 = min(u0 + UPC, NUNITS);
    if (u0 >= NUNITS) return;
    const int qt_a = u0 >> 3, qt_b = (u1 - 1) >> 3;

    float* lsum = (float*)(smem + S_LSUM);
    int* sflag  = (int*)(smem + S_LSUM + 128);

    // per-lane addressing (R6 geometry)
    const int rowA   = qrow0 + (lane & 15);
    const int selA   = lane >> 4;
    const int sb_row = ((lane >> 4) & 1) * 8 + (lane & 7);
    const int sb_sel = (lane >> 3) & 1;
    const int pv_row = lane & 15;
    const int pv_sel = lane >> 4;

    const uint32_t pair_base = sb + S_M + pw * PSTRIDE;

    for (int qt = qt_a; qt <= qt_b; ++qt) {
        const int s0 = max(u0, qt * 8) - qt * 8;
        const int s1 = min(u1, qt * 8 + 8) - qt * 8;
        const int t_beg = s0 * 8, t_end = s1 * 8;
        const int q0 = qt * BQ;
        const int slot = c - (8 * qt) / 7;           // 0 or 1, deterministic

        if (tid < 32) lsum[tid] = 0.f;

        // ---- load Q tile to smem, hoist A-fragments to registers ----
        for (int it = tid; it < 32 * 16; it += THREADS) {
            int row = it >> 4, ch = it & 15;
            uint32_t o = sw128((uint32_t)((ch >> 3) * 4096 + row * 128 + (ch & 7) * 16));
            *(uint4*)(smem + S_QH + o) = *(const uint4*)(g_q_h + (size_t)(q0 + row) * DD + ch * 8);
        }
        __syncthreads();

        uint32_t Aq[8][4];   // A(Q) fragments, resident for the whole segment
        #pragma unroll
        for (int k = 0; k < 8; ++k) {
            const int half = k >> 2;
            const int cb   = (k & 3) * 2;
            uint32_t ao = sw128((uint32_t)(half * 4096 + rowA * 128 + (cb + selA) * 16));
            ldsm_x4(Aq[k], sb + S_QH + ao);
        }

        float o_acc[16][4];
        #pragma unroll
        for (int nf = 0; nf < 16; ++nf)
            #pragma unroll
            for (int e = 0; e < 4; ++e) o_acc[nf][e] = 0.f;
        float rs0 = 0.f, rs1 = 0.f;

        const float* wbase = weights + (size_t)(q0 + qrow0 + gid) * MT + j0w + tig * 2;

        auto load_quarter = [&](int t, int buf) {
            const int m0 = t * BM + j0w;
            const uint32_t qb = pair_base + buf * STG;
            int it = tid & 63;
            #pragma unroll
            for (int rep = 0; rep < 8; ++rep, it += 64) {   // 512 items / 64 thr
                int row = it >> 4, ch = it & 15;
                uint32_t o = sw128((uint32_t)((ch >> 3) * 4096 + row * 128 + (ch & 7) * 16));
                CP_ASYNC16(qb + o, (const void*)(g_m_h + (size_t)(m0 + row) * DD + ch * 8));
            }
        };

        load_quarter(t_beg, t_beg & 1);
        CP_COMMIT();

        for (int t = t_beg; t < t_end; ++t) {
            CP_WAIT0();        // this warp's half of tile t landed
            BAR_PAIR(barid);   // partner's half landed; partner done reading
                               // the buffer we overwrite next (2-stage ring)
            if (t + 1 < t_end) load_quarter(t + 1, (t + 1) & 1);
            CP_COMMIT();

            const uint32_t mh = pair_base + (t & 1) * STG;

            // ---- weights prefetch, pre-scaled by 1/sqrt(d) ----
            float wreg[4][4];
            {
                const float* wp = wbase + (size_t)t * BM;
                #pragma unroll
                for (int nf = 0; nf < 4; ++nf) {
                    float2 w0 = *(const float2*)(wp + nf * 8);
                    float2 w1 = *(const float2*)(wp + nf * 8 + (size_t)8 * MT);
                    wreg[nf][0] = w0.x * SCALE; wreg[nf][1] = w0.y * SCALE;
                    wreg[nf][2] = w1.x * SCALE; wreg[nf][3] = w1.y * SCALE;
                }
            }

            // ---- S = Qh . Mh^T (16x32 per warp), 2-deep B pipeline ----
            float sf[4][4];
            #pragma unroll
            for (int nf = 0; nf < 4; ++nf)
                #pragma unroll
                for (int e = 0; e < 4; ++e) sf[nf][e] = 0.f;

            auto s_bo = [&](int k, int nfb) {
                const int half = k >> 2, cb = (k & 3) * 2;
                return sw128((uint32_t)(half * 4096 + (nfb * 8 + sb_row) * 128
                                        + (cb + sb_sel) * 16));
            };

            uint32_t Bh[2][8];
            ldsm_x4(Bh[0],     mh + s_bo(0, 0));
            ldsm_x4(Bh[0] + 4, mh + s_bo(0, 2));
            #pragma unroll
            for (int k = 0; k < 8; ++k) {
                const int cur = k & 1, nxt = cur ^ 1;
                if (k < 7) {
                    ldsm_x4(Bh[nxt],     mh + s_bo(k + 1, 0));
                    ldsm_x4(Bh[nxt] + 4, mh + s_bo(k + 1, 2));
                }
                #pragma unroll
                for (int nf = 0; nf < 4; ++nf) mma_f16(sf[nf], Aq[k], Bh[cur] + nf * 2);
            }

            // ---- weights * S, exp, pack P to fp16 A-fragments ----
            uint32_t aPh[2][4];
            #pragma unroll
            for (int nf = 0; nf < 4; ++nf) {
                float p[4];
                #pragma unroll
                for (int e = 0; e < 4; ++e) p[e] = __expf(sf[nf][e] * wreg[nf][e]);
                rs0 += p[0] + p[1];
                rs1 += p[2] + p[3];
                const int kf = nf >> 1;
                const int hi = (nf & 1) * 2;
                aPh[kf][hi]     = pack_h2(p[0], p[1]);
                aPh[kf][hi + 1] = pack_h2(p[2], p[3]);
            }

            // ---- O += Ph . Mh, 2-deep B pipeline (8 groups of nf-pairs) ----
            auto pv_bo = [&](int g) {   // g = kf*4 + nfg/4 : group of 4 nf
                const int kf = g >> 2, nfg = (g & 3) * 4;
                const int jb = (kf * 16 + pv_row) * 128;
                return (uint32_t)((nfg >> 3) * 4096 + jb);   // base; nf offset added below
            };

            uint32_t Ph[2][8];
            {
                const int jb0 = (0 * 16 + pv_row) * 128;
                ldsm_x4t(Ph[0],     mh + sw128((uint32_t)(jb0 + (0 + pv_sel) * 16)));
                ldsm_x4t(Ph[0] + 4, mh + sw128((uint32_t)(jb0 + (2 + pv_sel) * 16)));
            }
            #pragma unroll
            for (int g = 0; g < 8; ++g) {
                const int cur = g & 1, nxt = cur ^ 1;
                const int kf = g >> 2, nfg = (g & 3) * 4;
                if (g < 7) {
                    const int g2 = g + 1;
                    const int kf2 = g2 >> 2, nfg2 = (g2 & 3) * 4;
                    const int jb2 = (kf2 * 16 + pv_row) * 128;
                    ldsm_x4t(Ph[nxt],     mh + sw128((uint32_t)((nfg2 >> 3) * 4096 + jb2
                                              + (((nfg2 + 0) & 7) + pv_sel) * 16)));
                    ldsm_x4t(Ph[nxt] + 4, mh + sw128((uint32_t)(((nfg2 + 2) >> 3) * 4096 + jb2
                                              + (((nfg2 + 2) & 7) + pv_sel) * 16)));
                }
                #pragma unroll
                for (int nfb = 0; nfb < 4; ++nfb)
                    mma_f16(o_acc[nfg + nfb], aPh[kf], Ph[cur] + nfb * 2);
            }
            (void)pv_bo;
        }

        // ---- segment epilogue: reduce + write partial slab ----
        rs0 += __shfl_xor_sync(0xffffffffu, rs0, 1);
        rs0 += __shfl_xor_sync(0xffffffffu, rs0, 2);
        rs1 += __shfl_xor_sync(0xffffffffu, rs1, 1);
        rs1 += __shfl_xor_sync(0xffffffffu, rs1, 2);
        if (tig == 0) {
            atomicAdd(&lsum[qrow0 + gid], rs0);
            atomicAdd(&lsum[qrow0 + gid + 8], rs1);
        }
        __syncthreads();

        float* sO = (float*)(smem + S_M);   // reuse Mem region: [32][128] fp32
        for (int i = tid; i < 32 * 128; i += THREADS) sO[i] = 0.f;
        __syncthreads();
        #pragma unroll
        for (int nf = 0; nf < 16; ++nf) {
            const int cbase = nf * 8 + tig * 2;
            const int r0 = qrow0 + gid;
            atomicAdd(&sO[r0 * 128 + cbase],           o_acc[nf][0]);
            atomicAdd(&sO[r0 * 128 + cbase + 1],       o_acc[nf][1]);
            atomicAdd(&sO[(r0 + 8) * 128 + cbase],     o_acc[nf][2]);
            atomicAdd(&sO[(r0 + 8) * 128 + cbase + 1], o_acc[nf][3]);
        }
        __syncthreads();

        for (int i = tid; i < 32 * 32; i += THREADS) {
            int r  = i >> 5;
            int c4 = (i & 31) * 4;
            float4 v = *(float4*)(&sO[r * 128 + c4]);
            *(float4*)(&g_out_part[slot][(size_t)(q0 + r) * DD + c4]) = v;
        }
        if (tid < 32) g_lsum_part[slot][q0 + tid] = lsum[tid];
        __syncthreads();   // all slab writes issued

        // ---- last-finisher combine for this q-tile ----
        if (tid == 0) {
            __threadfence();
            sflag[0] = atomicAdd(&g_done[qt], 1);
        }
        __syncthreads();
        if (sflag[0] == 1) {
            __threadfence();
            for (int i = tid; i < 32 * 32; i += THREADS) {
                int r  = i >> 5;
                int c4 = (i & 31) * 4;
                int gr = q0 + r;
                float inv = 1.0f / (g_lsum_part[0][gr] + g_lsum_part[1][gr]);
                float4 a = *(float4*)(&g_out_part[0][(size_t)gr * DD + c4]);
                float4 b = *(float4*)(&g_out_part[1][(size_t)gr * DD + c4]);
                float4 v;
                v.x = (a.x + b.x) * inv; v.y = (a.y + b.y) * inv;
                v.z = (a.z + b.z) * inv; v.w = (a.w + b.w) * inv;
                *(float4*)(&out[(size_t)gr * DD + c4]) = v;
            }
        }
        __syncthreads();   // done with sO/lsum/sflag before next segment
    }
}

// ---------------- launch ----------------
extern "C" void kernel_launch(void* const* d_in, const int* in_sizes, int n_in,
                              void* d_out, int out_size)
{
    const float* query   = (const float*)d_in[0];
    const float* memory  = (const float*)d_in[1];
    const float* weights = (const float*)d_in[2];
    float* out = (float*)d_out;

    cudaFuncSetAttribute(attn_mma_kernel,
                         cudaFuncAttributeMaxDynamicSharedMemorySize, SMEM_TOTAL);

    prep_kernel<<<((QT + MT) * DD / 4 + 255) / 256, 256>>>(query, memory);
    attn_mma_kernel<<<NCTA, THREADS, SMEM_TOTAL>>>(weights, out);
}